// round 15
// baseline (speedup 1.0000x reference)
#include <cuda_runtime.h>

// Problem constants
#define BB 4
#define TT 16
#define NN 512
#define FF 5
#define HH 64
#define SS 2048           // B*N sequences
#define GG 256            // 4*H gates
#define R4 206            // RR/4 float4 per relation row
#define NSM 152           // GB300 SM count -> persistent 1 CTA/SM
#define NPAIR (NN*NN)     // 262144 relation pairs
#define NCHUNK (NPAIR/32) // 8192 32-pair chunks
// h layout: 16 seqs per k, 32B skew per 16-k block. For the four kb lane
// groups, start banks are kb*8+const -> disjoint 8-bank octets (conflict-free).
#define KOFF2(k) ((k)*16 + ((k)>>4)*8)
#define HBUF2 1056        // 63*16+3*8+16 = 1048, rounded up

typedef unsigned long long ull;

// Scratch (device globals; no allocation allowed).
// g_relw: only entries with rel_mask==0 are ever written; masked entries stay
// 0.0 (static zero-init) and are annihilated by the -1e9 mask in the softmax,
// exactly as in the reference (exp underflows to 0 in fp32). Deterministic.
__device__ float g_relw[NPAIR];
__device__ float g_tail[SS];      // leaky(out . fc3_w + fc3_b)
__device__ float g_q[SS];         // out . pred_w[64:128]
__device__ float g_p0[SS];        // out . pred_w[0:64]

// Grid-wide barrier (generation-based; replay-safe) + phase-1 work ticket.
__device__ unsigned int g_bar_count = 0;
__device__ unsigned int g_bar_gen   = 0;
__device__ unsigned int g_ticket    = 0;   // reset after barrier each launch

__device__ __forceinline__ float leaky(float v) { return v > 0.f ? v : 0.01f * v; }

// MUFU.TANH-based activations (sm_75+)
__device__ __forceinline__ float tanhft(float v) {
    float r;
    asm("tanh.approx.f32 %0, %1;" : "=f"(r) : "f"(v));
    return r;
}
__device__ __forceinline__ float sigm(float v) {
    float r;
    asm("tanh.approx.f32 %0, %1;" : "=f"(r) : "f"(0.5f * v));
    return 0.5f + 0.5f * r;
}

// packed f32x2 helpers (FFMA2/FADD2 — MOV-free operands from double2 loads)
__device__ __forceinline__ void fma2(ull& d, ull a, ull b) {
    asm("fma.rn.f32x2 %0, %1, %2, %3;" : "=l"(d) : "l"(a), "l"(b), "l"(d));
}
__device__ __forceinline__ ull add2(ull a, ull b) {
    ull d;
    asm("add.rn.f32x2 %0, %1, %2;" : "=l"(d) : "l"(a), "l"(b));
    return d;
}
__device__ __forceinline__ ull pack2(float lo, float hi) {
    ull r;
    asm("mov.b64 %0, {%1, %2};" : "=l"(r) : "f"(lo), "f"(hi));
    return r;
}
__device__ __forceinline__ void unpack2(ull a, float& lo, float& hi) {
    asm("mov.b64 {%0, %1}, %2;" : "=f"(lo), "=f"(hi) : "l"(a));
}
#define D2L __double_as_longlong

// One 824-length dot product, 32 lanes cooperating; returns lane-0 sum.
__device__ __forceinline__ float row_dot(const float4* __restrict__ row,
                                         const float4* __restrict__ wsm,
                                         int lane) {
    float4 a0 = __ldcs(row + lane);
    float4 a1 = __ldcs(row + lane + 32);
    float4 a2 = __ldcs(row + lane + 64);
    float4 a3 = __ldcs(row + lane + 96);
    float4 a4 = __ldcs(row + lane + 128);
    float4 a5 = __ldcs(row + lane + 160);
    float4 a6 = (lane < 14) ? __ldcs(row + lane + 192)
                            : make_float4(0.f, 0.f, 0.f, 0.f);
    float s = 0.f;
    float4 w;
    w = wsm[lane];       s += a0.x*w.x + a0.y*w.y + a0.z*w.z + a0.w*w.w;
    w = wsm[lane + 32];  s += a1.x*w.x + a1.y*w.y + a1.z*w.z + a1.w*w.w;
    w = wsm[lane + 64];  s += a2.x*w.x + a2.y*w.y + a2.z*w.z + a2.w*w.w;
    w = wsm[lane + 96];  s += a3.x*w.x + a3.y*w.y + a3.z*w.z + a3.w*w.w;
    w = wsm[lane + 128]; s += a4.x*w.x + a4.y*w.y + a4.z*w.z + a4.w*w.w;
    w = wsm[lane + 160]; s += a5.x*w.x + a5.y*w.y + a5.z*w.z + a5.w*w.w;
    if (lane < 14) {
        w = wsm[lane + 192];
        s += a6.x*w.x + a6.y*w.y + a6.z*w.z + a6.w*w.w;
    }
#pragma unroll
    for (int o = 16; o; o >>= 1) s += __shfl_xor_sync(0xffffffffu, s, o);
    return s;
}

// ---------------------------------------------------------------------------
// Persistent kernel: 152 CTAs x 512 threads (one per SM, one wave).
// Phase 1: sparse relw — ALL 16 warps drain the shared ticket pool (~14 us,
//          DRAM-floor bound; 3-row ballot batches).
// Phase 2: ONE wide LSTM engine — 16 warps, 16 seq slots, the 16-step
//          lockstep loop runs ONCE (v6 math: seq-packed FFMA2, fused
//          activation/update in registers, 1 __syncthreads per step,
//          h double-buffered). Warps 0-7 compute seqs 0-7; warps 8-15
//          compute seqs 8-15.
// Grid barrier, then phase 3: masked softmax + prediction (warp per row).
// ---------------------------------------------------------------------------
__global__ __launch_bounds__(512, 1) void fused_kernel(
    const float* __restrict__ x,
    const float* __restrict__ enc,
    const float* __restrict__ rel_mask,
    const float* __restrict__ Wih_f, const float* __restrict__ Whh_f,
    const float* __restrict__ bih_f, const float* __restrict__ bhh_f,
    const float* __restrict__ Wih_b,
    const float* __restrict__ bih_b, const float* __restrict__ bhh_b,
    const float* __restrict__ fc0_w, const float* __restrict__ fc0_b,
    const float* __restrict__ fc1_w, const float* __restrict__ fc1_b,
    const float* __restrict__ fc3_w, const float* __restrict__ fc3_b,
    const float* __restrict__ pred_w, const float* __restrict__ pred_b,
    float* __restrict__ out)
{
    __shared__ float4 wsm[R4];                  // fc1 weights
    __shared__ float wihs[GG * FF];             // Wih_f staged
    __shared__ float bsumS[GG];                 // bih_f + bhh_f
    __shared__ float xs[16 * TT * FF];          // 16 seqs x 16 x 5
    __shared__ __align__(16) float hb0[HBUF2], hb1[HBUF2];
    __shared__ __align__(16) float last[16 * 2 * HH];
    __shared__ float outb[16 * HH];

    int cta = blockIdx.x;
    int tid = threadIdx.x;
    int wid = tid >> 5, lane = tid & 31;

    // Snapshot barrier generation BEFORE any arrival can happen this launch.
    unsigned int my_gen = *((volatile unsigned int*)&g_bar_gen);

    // Stage shared weights (fc1, Wih_f, bias sums) once, all 512 threads.
    {
        const float4* w4g = (const float4*)fc1_w;
        for (int i = tid; i < R4; i += 512) wsm[i] = w4g[i];
        for (int i = tid; i < GG * FF; i += 512) wihs[i] = Wih_f[i];
        for (int i = tid; i < GG; i += 512) bsumS[i] = bih_f[i] + bhh_f[i];
    }
    __syncthreads();

    // ============ Phase 1: sparse relw — ALL 16 warps drain tickets ========
    {
        float fb = fc1_b[0];
        for (;;) {
            unsigned int tk;
            if (lane == 0) tk = atomicAdd(&g_ticket, 1u);
            tk = __shfl_sync(0xffffffffu, tk, 0);
            if (tk >= NCHUNK) break;
            int pb = (int)tk * 32;
            float mv = rel_mask[pb + lane];     // coalesced 128B load
            unsigned act = __ballot_sync(0xffffffffu, mv == 0.f);
            while (act) {
                // Up to 3 rows in flight (21 LDG.128) for deep MLP.
                int b0 = __ffs(act) - 1; act &= act - 1;
                int b1 = -1, b2 = -1;
                if (act) { b1 = __ffs(act) - 1; act &= act - 1; }
                if (act) { b2 = __ffs(act) - 1; act &= act - 1; }
                const float4* r0 = (const float4*)enc + (long long)(pb + b0) * R4;
                float s0 = row_dot(r0, (const float4*)wsm, lane);
                float s1 = 0.f, s2 = 0.f;
                if (b1 >= 0) {
                    const float4* r1 = (const float4*)enc + (long long)(pb + b1) * R4;
                    s1 = row_dot(r1, (const float4*)wsm, lane);
                }
                if (b2 >= 0) {
                    const float4* r2 = (const float4*)enc + (long long)(pb + b2) * R4;
                    s2 = row_dot(r2, (const float4*)wsm, lane);
                }
                if (lane == 0) {
                    g_relw[pb + b0] = leaky(s0 + fb);
                    if (b1 >= 0) g_relw[pb + b1] = leaky(s1 + fb);
                    if (b2 >= 0) g_relw[pb + b2] = leaky(s2 + fb);
                }
            }
        }
    }
    __syncthreads();

    // Sequence range: 2048 = 152*13 + 72  -> cnt = 13 or 14  (<= 16 slots)
    int base = 13 * cta + (cta < 72 ? cta : 72);
    int cnt  = 13 + (cta < 72 ? 1 : 0);

    // ============ Phase 2: ONE wide LSTM engine (16 warps, 16 slots) =======
    {
        const int sh   = wid >> 3;            // seq half: 0 -> seqs 0-7, 1 -> 8-15
        const int wl   = wid & 7;             // warp within half
        const int kb   = lane >> 3, gl = lane & 7;
        const int u    = wl * 8 + gl;         // this thread's unit 0..63
        const int kbase = kb * 16;            // this thread's k range
        // reduce-scatter final ownership within the half: local pair s0, s0+1
        const int s0l = ((lane & 8) ? 4 : 0) + ((lane & 16) ? 2 : 0);
        const int sA  = sh * 8 + s0l;         // global slot of owned pair
        const bool hi8  = (lane & 8)  != 0;
        const bool hi16 = (lane & 16) != 0;

        // Recurrent weights for gate rows {u, 64+u, 128+u, 192+u}
        float whr[4][16];
#pragma unroll
        for (int gt = 0; gt < 4; gt++) {
            const float4* wr = (const float4*)(Whh_f + (gt * HH + u) * HH + kbase);
#pragma unroll
            for (int q = 0; q < 4; q++) {
                float4 v = wr[q];
                whr[gt][4*q] = v.x; whr[gt][4*q+1] = v.y;
                whr[gt][4*q+2] = v.z; whr[gt][4*q+3] = v.w;
            }
        }
        // Input weights + bias for the same 4 gate rows (from smem staging)
        float wih[4][FF], bsum[4];
#pragma unroll
        for (int gt = 0; gt < 4; gt++) {
#pragma unroll
            for (int f = 0; f < FF; f++) wih[gt][f] = wihs[(gt * HH + u) * FF + f];
            bsum[gt] = bsumS[gt * HH + u];
        }

        // Stage x (zero-fill inactive slots), zero read-buffer h
        for (int i = tid; i < 16 * TT * FF; i += 512) {
            float v = 0.f;
            if (i < cnt * TT * FF) {
                int s = i / (TT * FF), r = i - s * (TT * FF);
                int t = r / FF, f = r - t * FF;
                int sg = base + s;
                int b = sg >> 9, n = sg & (NN - 1);
                v = x[((b * TT + t) * NN + n) * FF + f];
            }
            xs[i] = v;
        }
        for (int i = tid; i < HBUF2; i += 512) hb0[i] = 0.f;
        float c0 = 0.f, c1 = 0.f;        // cell state for (u,sA), (u,sA+1)
        float hA = 0.f, hB = 0.f;
        __syncthreads();

        // ---- forward recurrence: ONE barrier per step, h double-buffered --
#pragma unroll 1
        for (int t = 0; t < TT; t++) {
            const float* hr = (t & 1) ? hb1 : hb0;
            float*       hw = (t & 1) ? hb0 : hb1;

            // Packed accumulators over this half's 8 seqs
            ull acc2[4][4];
#pragma unroll
            for (int gt = 0; gt < 4; gt++)
#pragma unroll
                for (int p = 0; p < 4; p++) acc2[gt][p] = 0ull;

#pragma unroll
            for (int j = 0; j < 16; j++) {
                const double2* hp =
                    (const double2*)(hr + KOFF2(kbase + j) + sh * 8);
                double2 d0 = hp[0];        // local seqs 0,1 | 2,3
                double2 d1 = hp[1];        // local seqs 4,5 | 6,7
#pragma unroll
                for (int gt = 0; gt < 4; gt++) {
                    ull wp = pack2(whr[gt][j], whr[gt][j]);
                    fma2(acc2[gt][0], D2L(d0.x), wp);
                    fma2(acc2[gt][1], D2L(d0.y), wp);
                    fma2(acc2[gt][2], D2L(d1.x), wp);
                    fma2(acc2[gt][3], D2L(d1.y), wp);
                }
            }

            // Packed reduce-scatter (xor 8, xor 16) within the warp
            ull red[4];
#pragma unroll
            for (int gt = 0; gt < 4; gt++) {
                ull t2[2];
#pragma unroll
                for (int p = 0; p < 2; p++) {
                    ull send = hi8 ? acc2[gt][p]     : acc2[gt][p + 2];
                    ull keep = hi8 ? acc2[gt][p + 2] : acc2[gt][p];
                    t2[p] = add2(keep, __shfl_xor_sync(0xffffffffu, send, 8));
                }
                {
                    ull send = hi16 ? t2[0] : t2[1];
                    ull keep = hi16 ? t2[1] : t2[0];
                    red[gt] = add2(keep, __shfl_xor_sync(0xffffffffu, send, 16));
                }
            }

            // x-part + bias, then FUSED activation + cell update (registers)
            {
                const float* xtA = xs + sA * (TT * FF) + t * FF;
                const float* xtB = xtA + (TT * FF);
                float pA[4], pB[4];
#pragma unroll
                for (int gt = 0; gt < 4; gt++) {
                    float r0, r1;
                    unpack2(red[gt], r0, r1);
                    float a0 = r0 + bsum[gt];
                    float a1 = r1 + bsum[gt];
#pragma unroll
                    for (int f = 0; f < FF; f++) {
                        float wv = wih[gt][f];
                        a0 += xtA[f] * wv;
                        a1 += xtB[f] * wv;
                    }
                    pA[gt] = a0; pB[gt] = a1;
                }
                float iA = sigm(pA[0]), fA = sigm(pA[1]);
                float gA = tanhft(pA[2]), oA = sigm(pA[3]);
                c0 = fA * c0 + iA * gA;
                hA = oA * tanhft(c0);
                float iB = sigm(pB[0]), fB = sigm(pB[1]);
                float gB = tanhft(pB[2]), oB = sigm(pB[3]);
                c1 = fB * c1 + iB * gB;
                hB = oB * tanhft(c1);
                hw[KOFF2(u) + sA]     = hA;
                hw[KOFF2(u) + sA + 1] = hB;
            }
            __syncthreads();
        }

        // h_fwd -> last[:, 0:64] (straight from registers)
        last[sA * 2 * HH + u]       = hA;
        last[(sA + 1) * 2 * HH + u] = hB;

        // ---- backward LSTM: one step from zero state on x[T-1] ----
        {
            const float* xtA = xs + sA * (TT * FF) + (TT - 1) * FF;
            const float* xtB = xtA + (TT * FF);
            float pA[4], pB[4];
#pragma unroll
            for (int gt = 0; gt < 4; gt++) {
                if (gt == 1) continue;           // forget gate irrelevant
                float bb = bih_b[gt * HH + u] + bhh_b[gt * HH + u];
                float a0 = bb, a1 = bb;
#pragma unroll
                for (int f = 0; f < FF; f++) {
                    float wv = Wih_b[(gt * HH + u) * FF + f];
                    a0 += xtA[f] * wv;
                    a1 += xtB[f] * wv;
                }
                pA[gt] = a0; pB[gt] = a1;
            }
            float iA = sigm(pA[0]), gA = tanhft(pA[2]), oA = sigm(pA[3]);
            float iB = sigm(pB[0]), gB = tanhft(pB[2]), oB = sigm(pB[3]);
            last[sA * 2 * HH + HH + u]       = oA * tanhft(iA * gA); // f*c0=0
            last[(sA + 1) * 2 * HH + HH + u] = oB * tanhft(iB * gB);
        }
        __syncthreads();

        // ---- fc0 + leaky: thread handles (su,uu) and (su+8,uu) ----
        {
            const int uu = tid & 63, su = tid >> 6;   // su 0..7
            const float4* w4 = (const float4*)(fc0_w + uu * 2 * HH);
            const float4* la = (const float4*)(last + su * 2 * HH);
            const float4* lb = (const float4*)(last + (su + 8) * 2 * HH);
            float a0 = 0.f, a1 = 0.f, b0 = 0.f, b1 = 0.f;
#pragma unroll
            for (int j = 0; j < 2 * HH / 4; j++) {
                float4 wv = w4[j];
                float4 va = la[j], vb = lb[j];
                a0 += wv.x * va.x + wv.y * va.y;
                a1 += wv.z * va.z + wv.w * va.w;
                b0 += wv.x * vb.x + wv.y * vb.y;
                b1 += wv.z * vb.z + wv.w * vb.w;
            }
            float fb = fc0_b[uu];
            outb[su * HH + uu]       = leaky(fb + a0 + a1);
            outb[(su + 8) * HH + uu] = leaky(fb + b0 + b1);
        }
        __syncthreads();

        // ---- epilogue scalars: one warp per sequence (3 dots fused) ----
        if (wid < cnt) {
            int sg = base + wid;
            const float* o = outb + wid * HH;
            float o_lo = o[lane], o_hi = o[lane + 32];
            float v0 = o_lo * fc3_w[lane]        + o_hi * fc3_w[lane + 32];
            float v1 = o_lo * pred_w[HH + lane]  + o_hi * pred_w[HH + lane + 32];
            float v2 = o_lo * pred_w[lane]       + o_hi * pred_w[lane + 32];
#pragma unroll
            for (int off = 16; off; off >>= 1) {
                v0 += __shfl_xor_sync(0xffffffffu, v0, off);
                v1 += __shfl_xor_sync(0xffffffffu, v1, off);
                v2 += __shfl_xor_sync(0xffffffffu, v2, off);
            }
            if (lane == 0) {
                g_tail[sg] = leaky(v0 + fc3_b[0]);
                g_q[sg]    = v1;
                g_p0[sg]   = v2;
            }
        }
    }

    // ===================== Grid-wide barrier ===============================
    __threadfence();                    // publish g_relw/g_tail/g_q/g_p0
    __syncthreads();
    if (tid == 0) {
        unsigned int old = atomicAdd(&g_bar_count, 1u);
        if (old == NSM - 1) {
            g_bar_count = 0;            // all CTAs have arrived
            g_ticket = 0;               // reset work ticket for next launch
            __threadfence();
            atomicAdd(&g_bar_gen, 1u);  // release
        }
        while (*((volatile unsigned int*)&g_bar_gen) == my_gen) { }
    }
    __syncthreads();
    __threadfence();                    // acquire

    // ====== Phase 3: masked softmax + prediction (one warp per row) ========
    if (wid < cnt) {
        int sg = base + wid;
        int b = sg >> 9, n = sg & (NN - 1);
        const float4* m4 = (const float4*)(rel_mask + (long long)n * NN);
        const float4* r4 = (const float4*)(g_relw  + (long long)n * NN);
        const float4* t4 = (const float4*)(g_tail + b * NN);
        const float4* q4 = (const float4*)(g_q    + b * NN);

        float4 l[4];
        float mx = -1e30f;
#pragma unroll
        for (int j = 0; j < 4; j++) {
            int idx = j * 32 + lane;
            float4 mv = m4[idx], rv = r4[idx], tv = t4[idx];
            l[j].x = mv.x + rv.x + tv.x;
            l[j].y = mv.y + rv.y + tv.y;
            l[j].z = mv.z + rv.z + tv.z;
            l[j].w = mv.w + rv.w + tv.w;
            mx = fmaxf(mx, fmaxf(fmaxf(l[j].x, l[j].y), fmaxf(l[j].z, l[j].w)));
        }
#pragma unroll
        for (int o = 16; o; o >>= 1) mx = fmaxf(mx, __shfl_xor_sync(0xffffffffu, mx, o));

        float se = 0.f, sq = 0.f;
#pragma unroll
        for (int j = 0; j < 4; j++) {
            int idx = j * 32 + lane;
            float4 qv = q4[idx];
            float e0 = __expf(l[j].x - mx);
            float e1 = __expf(l[j].y - mx);
            float e2 = __expf(l[j].z - mx);
            float e3 = __expf(l[j].w - mx);
            se += (e0 + e1) + (e2 + e3);
            sq += (e0 * qv.x + e1 * qv.y) + (e2 * qv.z + e3 * qv.w);
        }
#pragma unroll
        for (int o = 16; o; o >>= 1) {
            se += __shfl_xor_sync(0xffffffffu, se, o);
            sq += __shfl_xor_sync(0xffffffffu, sq, o);
        }
        if (lane == 0)
            out[sg] = leaky(g_p0[sg] + sq / se + pred_b[0]);
    }
}

// ---------------------------------------------------------------------------
extern "C" void kernel_launch(void* const* d_in, const int* in_sizes, int n_in,
                              void* d_out, int out_size) {
    const float* x      = (const float*)d_in[0];
    const float* enc    = (const float*)d_in[1];
    const float* mask   = (const float*)d_in[2];
    const float* Wih_f  = (const float*)d_in[3];
    const float* Whh_f  = (const float*)d_in[4];
    const float* bih_f  = (const float*)d_in[5];
    const float* bhh_f  = (const float*)d_in[6];
    const float* Wih_b  = (const float*)d_in[7];
    // d_in[8] (Whh_b) unused: backward LSTM runs exactly one step from zero state
    const float* bih_b  = (const float*)d_in[9];
    const float* bhh_b  = (const float*)d_in[10];
    const float* fc0_w  = (const float*)d_in[11];
    const float* fc0_b  = (const float*)d_in[12];
    const float* fc1_w  = (const float*)d_in[13];
    const float* fc1_b  = (const float*)d_in[14];
    // d_in[15..16] (fc2) unused: head term is constant over softmax axis
    const float* fc3_w  = (const float*)d_in[17];
    const float* fc3_b  = (const float*)d_in[18];
    const float* pred_w = (const float*)d_in[19];
    const float* pred_b = (const float*)d_in[20];
    float* out = (float*)d_out;

    fused_kernel<<<NSM, 512>>>(x, enc, mask, Wih_f, Whh_f, bih_f, bhh_f,
                               Wih_b, bih_b, bhh_b,
                               fc0_w, fc0_b, fc1_w, fc1_b, fc3_w, fc3_b,
                               pred_w, pred_b, out);
}

// round 16
// speedup vs baseline: 1.0652x; 1.0652x over previous
#include <cuda_runtime.h>

// Problem constants
#define BB 4
#define TT 16
#define NN 512
#define FF 5
#define HH 64
#define SS 2048           // B*N sequences
#define GG 256            // 4*H gates
#define R4 206            // RR/4 float4 per relation row
#define NSM 152           // GB300 SM count -> persistent 1 CTA/SM
#define NPAIR (NN*NN)     // 262144 relation pairs
#define NCHUNK (NPAIR/32) // 8192 32-pair chunks
// h k-major layout with 16B skew per 16-k block: conflict-free kb access
#define KOFF(k) ((k)*8 + ((k)>>4)*4)
#define HBUF 544          // one h buffer (64 k * 8 seqs + skew)

typedef unsigned long long ull;

// Scratch (device globals; no allocation allowed).
// g_relw: only entries with rel_mask==0 are ever written; masked entries stay
// 0.0 (static zero-init) and are annihilated by the -1e9 mask in the softmax,
// exactly as in the reference (exp underflows to 0 in fp32). Deterministic.
__device__ float g_relw[NPAIR];
__device__ float g_tail[SS];      // leaky(out . fc3_w + fc3_b)
__device__ float g_q[SS];         // out . pred_w[64:128]
__device__ float g_p0[SS];        // out . pred_w[0:64]

// Grid-wide barrier (generation-based; replay-safe) + phase-1 work ticket.
__device__ unsigned int g_bar_count = 0;
__device__ unsigned int g_bar_gen   = 0;
__device__ unsigned int g_ticket    = 0;   // reset after barrier each launch

__device__ __forceinline__ float leaky(float v) { return v > 0.f ? v : 0.01f * v; }

// MUFU.TANH-based activations (sm_75+): tanh = 1 MUFU; sigmoid via
// 0.5 + 0.5*tanh(x/2) = 1 MUFU + 2 FMA.
__device__ __forceinline__ float tanhft(float v) {
    float r;
    asm("tanh.approx.f32 %0, %1;" : "=f"(r) : "f"(v));
    return r;
}
__device__ __forceinline__ float sigm(float v) {
    float r;
    asm("tanh.approx.f32 %0, %1;" : "=f"(r) : "f"(0.5f * v));
    return 0.5f + 0.5f * r;
}

__device__ __forceinline__ void barn(int id, int cnt) {
    asm volatile("bar.sync %0, %1;" :: "r"(id), "r"(cnt) : "memory");
}

// packed f32x2 helpers (FFMA2/FADD2 — MOV-free operands from double2 loads)
__device__ __forceinline__ void fma2(ull& d, ull a, ull b) {
    asm("fma.rn.f32x2 %0, %1, %2, %3;" : "=l"(d) : "l"(a), "l"(b), "l"(d));
}
__device__ __forceinline__ ull add2(ull a, ull b) {
    ull d;
    asm("add.rn.f32x2 %0, %1, %2;" : "=l"(d) : "l"(a), "l"(b));
    return d;
}
__device__ __forceinline__ ull pack2(float lo, float hi) {
    ull r;
    asm("mov.b64 %0, {%1, %2};" : "=l"(r) : "f"(lo), "f"(hi));
    return r;
}
__device__ __forceinline__ void unpack2(ull a, float& lo, float& hi) {
    asm("mov.b64 {%0, %1}, %2;" : "=f"(lo), "=f"(hi) : "l"(a));
}
#define D2L __double_as_longlong

// One 824-length dot product, 32 lanes cooperating; returns lane-0 sum.
__device__ __forceinline__ float row_dot(const float4* __restrict__ row,
                                         const float4* __restrict__ wsm,
                                         int lane) {
    float4 a0 = __ldcs(row + lane);
    float4 a1 = __ldcs(row + lane + 32);
    float4 a2 = __ldcs(row + lane + 64);
    float4 a3 = __ldcs(row + lane + 96);
    float4 a4 = __ldcs(row + lane + 128);
    float4 a5 = __ldcs(row + lane + 160);
    float4 a6 = (lane < 14) ? __ldcs(row + lane + 192)
                            : make_float4(0.f, 0.f, 0.f, 0.f);
    float s = 0.f;
    float4 w;
    w = wsm[lane];       s += a0.x*w.x + a0.y*w.y + a0.z*w.z + a0.w*w.w;
    w = wsm[lane + 32];  s += a1.x*w.x + a1.y*w.y + a1.z*w.z + a1.w*w.w;
    w = wsm[lane + 64];  s += a2.x*w.x + a2.y*w.y + a2.z*w.z + a2.w*w.w;
    w = wsm[lane + 96];  s += a3.x*w.x + a3.y*w.y + a3.z*w.z + a3.w*w.w;
    w = wsm[lane + 128]; s += a4.x*w.x + a4.y*w.y + a4.z*w.z + a4.w*w.w;
    w = wsm[lane + 160]; s += a5.x*w.x + a5.y*w.y + a5.z*w.z + a5.w*w.w;
    if (lane < 14) {
        w = wsm[lane + 192];
        s += a6.x*w.x + a6.y*w.y + a6.z*w.z + a6.w*w.w;
    }
#pragma unroll
    for (int o = 16; o; o >>= 1) s += __shfl_xor_sync(0xffffffffu, s, o);
    return s;
}

// ---------------------------------------------------------------------------
// LSTM engine v8: v6 (R12/R14) + software-pipelined x-part.
// 256 threads, up to 8 sequences. Seq-packed FFMA2 recurrence; fused
// activation/update in registers; 1 barrier/step; h double-buffered.
// xp[t+1] is computed after the h-store, BEFORE the barrier (fills the
// barrier bubble; removes ~25 instrs from the post-reduce serial chain).
// ---------------------------------------------------------------------------
__device__ __forceinline__ void lstm_engine(
    int t256, int sbase, int ns,
    const float* __restrict__ x,
    const float* __restrict__ Whh_f,
    const float* __restrict__ Wih_b,
    const float* __restrict__ bih_b, const float* __restrict__ bhh_b,
    const float* __restrict__ fc0_w, const float* __restrict__ fc0_b,
    const float* __restrict__ fc3_w, const float* __restrict__ fc3_b,
    const float* __restrict__ pred_w,
    const float* __restrict__ wihs,   // smem [GG*FF]
    const float* __restrict__ bsumS,  // smem [GG] (bih_f+bhh_f)
    float* __restrict__ xs,      // [8*TT*FF]
    float* __restrict__ hb0,     // [HBUF] h buffer 0 (read at even t)
    float* __restrict__ hb1,     // [HBUF] h buffer 1
    float* __restrict__ last,    // [8*2*HH]
    float* __restrict__ outb,    // [8*HH]
    int barid)
{
    const int w    = t256 >> 5, lane = t256 & 31;
    const int kb   = lane >> 3, gl   = lane & 7;
    const int u    = w * 8 + gl;           // this thread's unit 0..63
    const int kbase = kb * 16;             // this thread's k range
    // reduce-scatter final ownership: seqs s0, s0+1 (a packed pair)
    const int s0 = ((lane & 8) ? 4 : 0) + ((lane & 16) ? 2 : 0);
    const bool hi8  = (lane & 8)  != 0;
    const bool hi16 = (lane & 16) != 0;

    // Recurrent weights for gate rows {u, 64+u, 128+u, 192+u}, k-range kbase..
    float whr[4][16];
#pragma unroll
    for (int gt = 0; gt < 4; gt++) {
        const float4* wr = (const float4*)(Whh_f + (gt * HH + u) * HH + kbase);
#pragma unroll
        for (int q = 0; q < 4; q++) {
            float4 v = wr[q];
            whr[gt][4*q] = v.x; whr[gt][4*q+1] = v.y;
            whr[gt][4*q+2] = v.z; whr[gt][4*q+3] = v.w;
        }
    }
    // Input weights + bias for the same 4 gate rows (from smem staging)
    float wih[4][FF], bsum[4];
#pragma unroll
    for (int gt = 0; gt < 4; gt++) {
#pragma unroll
        for (int f = 0; f < FF; f++) wih[gt][f] = wihs[(gt * HH + u) * FF + f];
        bsum[gt] = bsumS[gt * HH + u];
    }

    // Stage x (zero-fill inactive seqs), zero read-buffer h
    for (int i = t256; i < 8 * TT * FF; i += 256) {
        float v = 0.f;
        if (i < ns * TT * FF) {
            int s = i / (TT * FF), r = i - s * (TT * FF);
            int t = r / FF, f = r - t * FF;
            int sg = sbase + s;
            int b = sg >> 9, n = sg & (NN - 1);
            v = x[((b * TT + t) * NN + n) * FF + f];
        }
        xs[i] = v;
    }
    for (int i = t256; i < HBUF; i += 256) hb0[i] = 0.f;
    float c0 = 0.f, c1 = 0.f;        // cell state for (u,s0), (u,s0+1)
    float hA = 0.f, hB = 0.f;        // final h values (kept for 'last')
    barn(barid, 256);

    // Pipelined x-part for t=0
    float xpA[4], xpB[4];
    {
        const float* xtA = xs + s0 * (TT * FF);
        const float* xtB = xtA + (TT * FF);
#pragma unroll
        for (int gt = 0; gt < 4; gt++) {
            float a0 = bsum[gt], a1 = bsum[gt];
#pragma unroll
            for (int f = 0; f < FF; f++) {
                float wv = wih[gt][f];
                a0 += xtA[f] * wv;
                a1 += xtB[f] * wv;
            }
            xpA[gt] = a0; xpB[gt] = a1;
        }
    }

    // ---- forward recurrence: ONE barrier per step, h double-buffered ----
#pragma unroll 1
    for (int t = 0; t < TT; t++) {
        const float* hr = (t & 1) ? hb1 : hb0;   // read buffer
        float*       hw = (t & 1) ? hb0 : hb1;   // write buffer

        // Packed accumulators: acc2[gt][p] = f32x2 sums for seqs (2p, 2p+1)
        ull acc2[4][4];
#pragma unroll
        for (int gt = 0; gt < 4; gt++)
#pragma unroll
            for (int p = 0; p < 4; p++) acc2[gt][p] = 0ull;

#pragma unroll
        for (int j = 0; j < 16; j++) {
            const double2* hp = (const double2*)(hr + KOFF(kbase + j));
            double2 d0 = hp[0];            // pairs (s0,s1), (s2,s3)
            double2 d1 = hp[1];            // pairs (s4,s5), (s6,s7)
#pragma unroll
            for (int gt = 0; gt < 4; gt++) {
                ull wp = pack2(whr[gt][j], whr[gt][j]);
                fma2(acc2[gt][0], D2L(d0.x), wp);
                fma2(acc2[gt][1], D2L(d0.y), wp);
                fma2(acc2[gt][2], D2L(d1.x), wp);
                fma2(acc2[gt][3], D2L(d1.y), wp);
            }
        }

        // Packed reduce-scatter over the 4 kb lane-groups (xor 8, xor 16):
        // lane ends with ONE packed pair = full sums for (s0, s0+1).
        ull red[4];
#pragma unroll
        for (int gt = 0; gt < 4; gt++) {
            ull t2[2];
#pragma unroll
            for (int p = 0; p < 2; p++) {
                ull send = hi8 ? acc2[gt][p]     : acc2[gt][p + 2];
                ull keep = hi8 ? acc2[gt][p + 2] : acc2[gt][p];
                t2[p] = add2(keep, __shfl_xor_sync(0xffffffffu, send, 8));
            }
            {
                ull send = hi16 ? t2[0] : t2[1];
                ull keep = hi16 ? t2[1] : t2[0];
                red[gt] = add2(keep, __shfl_xor_sync(0xffffffffu, send, 16));
            }
        }

        // FUSED activation + cell update (x-part already in xpA/xpB)
        {
            float pA[4], pB[4];
#pragma unroll
            for (int gt = 0; gt < 4; gt++) {
                float r0, r1;
                unpack2(red[gt], r0, r1);
                pA[gt] = r0 + xpA[gt];
                pB[gt] = r1 + xpB[gt];
            }
            float iA = sigm(pA[0]), fA = sigm(pA[1]);
            float gA = tanhft(pA[2]), oA = sigm(pA[3]);
            c0 = fA * c0 + iA * gA;
            hA = oA * tanhft(c0);
            float iB = sigm(pB[0]), fB = sigm(pB[1]);
            float gB = tanhft(pB[2]), oB = sigm(pB[3]);
            c1 = fB * c1 + iB * gB;
            hB = oB * tanhft(c1);
            hw[KOFF(u) + s0]     = hA;
            hw[KOFF(u) + s0 + 1] = hB;
        }

        // Pipelined x-part for t+1 (fills the barrier bubble; no h dep)
        if (t < TT - 1) {
            const float* xtA = xs + s0 * (TT * FF) + (t + 1) * FF;
            const float* xtB = xtA + (TT * FF);
#pragma unroll
            for (int gt = 0; gt < 4; gt++) {
                float a0 = bsum[gt], a1 = bsum[gt];
#pragma unroll
                for (int f = 0; f < FF; f++) {
                    float wv = wih[gt][f];
                    a0 += xtA[f] * wv;
                    a1 += xtB[f] * wv;
                }
                xpA[gt] = a0; xpB[gt] = a1;
            }
        }
        barn(barid, 256);
    }

    // h_fwd -> last[:, 0:64] (straight from registers)
    last[s0 * 2 * HH + u]       = hA;
    last[(s0 + 1) * 2 * HH + u] = hB;

    // ---- backward LSTM: one step from zero state on x[T-1] (f unused) ----
    {
        const float* xtA = xs + s0 * (TT * FF) + (TT - 1) * FF;
        const float* xtB = xtA + (TT * FF);
        float pA[4], pB[4];
#pragma unroll
        for (int gt = 0; gt < 4; gt++) {
            if (gt == 1) continue;               // forget gate irrelevant
            float bb = bih_b[gt * HH + u] + bhh_b[gt * HH + u];
            float a0 = bb, a1 = bb;
#pragma unroll
            for (int f = 0; f < FF; f++) {
                float wv = Wih_b[(gt * HH + u) * FF + f];
                a0 += xtA[f] * wv;
                a1 += xtB[f] * wv;
            }
            pA[gt] = a0; pB[gt] = a1;
        }
        float iA = sigm(pA[0]), gA = tanhft(pA[2]), oA = sigm(pA[3]);
        float iB = sigm(pB[0]), gB = tanhft(pB[2]), oB = sigm(pB[3]);
        last[s0 * 2 * HH + HH + u]       = oA * tanhft(iA * gA);  // f*c0 = 0
        last[(s0 + 1) * 2 * HH + HH + u] = oB * tanhft(iB * gB);
    }
    barn(barid, 256);

    // ---- fc0 + leaky: threads (su,uu) and (su+4,uu) ----
    {
        const int uu = t256 & 63, su = t256 >> 6;
        const float4* w4 = (const float4*)(fc0_w + uu * 2 * HH);
        const float4* la = (const float4*)(last + su * 2 * HH);
        const float4* lb = (const float4*)(last + (su + 4) * 2 * HH);
        float a0 = 0.f, a1 = 0.f, b0 = 0.f, b1 = 0.f;
#pragma unroll
        for (int j = 0; j < 2 * HH / 4; j++) {
            float4 wv = w4[j];
            float4 va = la[j], vb = lb[j];
            a0 += wv.x * va.x + wv.y * va.y;
            a1 += wv.z * va.z + wv.w * va.w;
            b0 += wv.x * vb.x + wv.y * vb.y;
            b1 += wv.z * vb.z + wv.w * vb.w;
        }
        float fb = fc0_b[uu];
        outb[su * HH + uu]       = leaky(fb + a0 + a1);
        outb[(su + 4) * HH + uu] = leaky(fb + b0 + b1);
    }
    barn(barid, 256);

    // ---- epilogue scalars: one warp per sequence (3 dots fused) ----
    if (w < ns) {
        int sg = sbase + w;
        const float* o = outb + w * HH;
        float o_lo = o[lane], o_hi = o[lane + 32];
        float v0 = o_lo * fc3_w[lane]        + o_hi * fc3_w[lane + 32];
        float v1 = o_lo * pred_w[HH + lane]  + o_hi * pred_w[HH + lane + 32];
        float v2 = o_lo * pred_w[lane]       + o_hi * pred_w[lane + 32];
#pragma unroll
        for (int off = 16; off; off >>= 1) {
            v0 += __shfl_xor_sync(0xffffffffu, v0, off);
            v1 += __shfl_xor_sync(0xffffffffu, v1, off);
            v2 += __shfl_xor_sync(0xffffffffu, v2, off);
        }
        if (lane == 0) {
            g_tail[sg] = leaky(v0 + fc3_b[0]);
            g_q[sg]    = v1;
            g_p0[sg]   = v2;
        }
    }
}

// ---------------------------------------------------------------------------
// Persistent kernel: 152 CTAs x 512 threads (one per SM, one wave).
//   warps 0-7 : LSTM engine A (seqs 0..7 of this CTA) immediately.
//   warps 8-15: sparse relw (ticket + ballot, 3-row batches), THEN engine B.
// Grid barrier, then phase 3: masked softmax + prediction (warp per row).
// ---------------------------------------------------------------------------
__global__ __launch_bounds__(512, 1) void fused_kernel(
    const float* __restrict__ x,
    const float* __restrict__ enc,
    const float* __restrict__ rel_mask,
    const float* __restrict__ Wih_f, const float* __restrict__ Whh_f,
    const float* __restrict__ bih_f, const float* __restrict__ bhh_f,
    const float* __restrict__ Wih_b,
    const float* __restrict__ bih_b, const float* __restrict__ bhh_b,
    const float* __restrict__ fc0_w, const float* __restrict__ fc0_b,
    const float* __restrict__ fc1_w, const float* __restrict__ fc1_b,
    const float* __restrict__ fc3_w, const float* __restrict__ fc3_b,
    const float* __restrict__ pred_w, const float* __restrict__ pred_b,
    float* __restrict__ out)
{
    __shared__ float4 wsm[R4];                  // fc1 weights
    __shared__ float wihs[GG * FF];             // Wih_f staged
    __shared__ float bsumS[GG];                 // bih_f + bhh_f
    __shared__ float xsA[8 * TT * FF], xsB[8 * TT * FF];
    __shared__ __align__(16) float h0A[HBUF], h1A[HBUF];
    __shared__ __align__(16) float h0B[HBUF], h1B[HBUF];
    __shared__ __align__(16) float lastA[8 * 2 * HH], lastB[8 * 2 * HH];
    __shared__ float outA[8 * HH], outB[8 * HH];

    int cta = blockIdx.x;
    int tid = threadIdx.x;
    int wid = tid >> 5, lane = tid & 31;

    // Snapshot barrier generation BEFORE any arrival can happen this launch.
    unsigned int my_gen = *((volatile unsigned int*)&g_bar_gen);

    // Stage shared weights (fc1, Wih_f, bias sums) once, all 512 threads.
    {
        const float4* w4g = (const float4*)fc1_w;
        for (int i = tid; i < R4; i += 512) wsm[i] = w4g[i];
        for (int i = tid; i < GG * FF; i += 512) wihs[i] = Wih_f[i];
        for (int i = tid; i < GG; i += 512) bsumS[i] = bih_f[i] + bhh_f[i];
    }
    __syncthreads();

    // Sequence range: 2048 = 152*13 + 72  -> cnt = 13 or 14
    int base = 13 * cta + (cta < 72 ? cta : 72);
    int cnt  = 13 + (cta < 72 ? 1 : 0);

    if (wid < 8) {
        // ============ Half A: LSTM engine A (seqs 0..7) ====================
        lstm_engine(tid, base, 8, x, Whh_f, Wih_b, bih_b, bhh_b,
                    fc0_w, fc0_b, fc3_w, fc3_b, pred_w, wihs, bsumS,
                    xsA, h0A, h1A, lastA, outA, /*barid=*/1);
    } else {
        // ============ Half B: sparse relw, then LSTM engine B ==============
        {
            float fb = fc1_b[0];
            for (;;) {
                unsigned int tk;
                if (lane == 0) tk = atomicAdd(&g_ticket, 1u);
                tk = __shfl_sync(0xffffffffu, tk, 0);
                if (tk >= NCHUNK) break;
                int pb = (int)tk * 32;
                float mv = rel_mask[pb + lane];     // coalesced 128B load
                unsigned act = __ballot_sync(0xffffffffu, mv == 0.f);
                while (act) {
                    // Up to 3 rows in flight (21 LDG.128) for deep MLP.
                    int b0 = __ffs(act) - 1; act &= act - 1;
                    int b1 = -1, b2 = -1;
                    if (act) { b1 = __ffs(act) - 1; act &= act - 1; }
                    if (act) { b2 = __ffs(act) - 1; act &= act - 1; }
                    const float4* r0 = (const float4*)enc + (long long)(pb + b0) * R4;
                    float s0 = row_dot(r0, (const float4*)wsm, lane);
                    float s1 = 0.f, s2 = 0.f;
                    if (b1 >= 0) {
                        const float4* r1 = (const float4*)enc + (long long)(pb + b1) * R4;
                        s1 = row_dot(r1, (const float4*)wsm, lane);
                    }
                    if (b2 >= 0) {
                        const float4* r2 = (const float4*)enc + (long long)(pb + b2) * R4;
                        s2 = row_dot(r2, (const float4*)wsm, lane);
                    }
                    if (lane == 0) {
                        g_relw[pb + b0] = leaky(s0 + fb);
                        if (b1 >= 0) g_relw[pb + b1] = leaky(s1 + fb);
                        if (b2 >= 0) g_relw[pb + b2] = leaky(s2 + fb);
                    }
                }
            }
        }
        // Engine B: remaining cnt-8 sequences (5 or 6)
        lstm_engine(tid - 256, base + 8, cnt - 8, x, Whh_f, Wih_b, bih_b, bhh_b,
                    fc0_w, fc0_b, fc3_w, fc3_b, pred_w, wihs, bsumS,
                    xsB, h0B, h1B, lastB, outB, /*barid=*/2);
    }

    // ===================== Grid-wide barrier ===============================
    __threadfence();                    // publish g_relw/g_tail/g_q/g_p0
    __syncthreads();                    // join the two halves
    if (tid == 0) {
        unsigned int old = atomicAdd(&g_bar_count, 1u);
        if (old == NSM - 1) {
            g_bar_count = 0;            // all CTAs have arrived
            g_ticket = 0;               // reset work ticket for next launch
            __threadfence();
            atomicAdd(&g_bar_gen, 1u);  // release
        }
        while (*((volatile unsigned int*)&g_bar_gen) == my_gen) { }
    }
    __syncthreads();
    __threadfence();                    // acquire

    // ====== Phase 3: masked softmax + prediction (one warp per row) ========
    if (wid < cnt) {
        int sg = base + wid;
        int b = sg >> 9, n = sg & (NN - 1);
        const float4* m4 = (const float4*)(rel_mask + (long long)n * NN);
        const float4* r4 = (const float4*)(g_relw  + (long long)n * NN);
        const float4* t4 = (const float4*)(g_tail + b * NN);
        const float4* q4 = (const float4*)(g_q    + b * NN);

        float4 l[4];
        float mx = -1e30f;
#pragma unroll
        for (int j = 0; j < 4; j++) {
            int idx = j * 32 + lane;
            float4 mv = m4[idx], rv = r4[idx], tv = t4[idx];
            l[j].x = mv.x + rv.x + tv.x;
            l[j].y = mv.y + rv.y + tv.y;
            l[j].z = mv.z + rv.z + tv.z;
            l[j].w = mv.w + rv.w + tv.w;
            mx = fmaxf(mx, fmaxf(fmaxf(l[j].x, l[j].y), fmaxf(l[j].z, l[j].w)));
        }
#pragma unroll
        for (int o = 16; o; o >>= 1) mx = fmaxf(mx, __shfl_xor_sync(0xffffffffu, mx, o));

        float se = 0.f, sq = 0.f;
#pragma unroll
        for (int j = 0; j < 4; j++) {
            int idx = j * 32 + lane;
            float4 qv = q4[idx];
            float e0 = __expf(l[j].x - mx);
            float e1 = __expf(l[j].y - mx);
            float e2 = __expf(l[j].z - mx);
            float e3 = __expf(l[j].w - mx);
            se += (e0 + e1) + (e2 + e3);
            sq += (e0 * qv.x + e1 * qv.y) + (e2 * qv.z + e3 * qv.w);
        }
#pragma unroll
        for (int o = 16; o; o >>= 1) {
            se += __shfl_xor_sync(0xffffffffu, se, o);
            sq += __shfl_xor_sync(0xffffffffu, sq, o);
        }
        if (lane == 0)
            out[sg] = leaky(g_p0[sg] + sq / se + pred_b[0]);
    }
}

// ---------------------------------------------------------------------------
extern "C" void kernel_launch(void* const* d_in, const int* in_sizes, int n_in,
                              void* d_out, int out_size) {
    const float* x      = (const float*)d_in[0];
    const float* enc    = (const float*)d_in[1];
    const float* mask   = (const float*)d_in[2];
    const float* Wih_f  = (const float*)d_in[3];
    const float* Whh_f  = (const float*)d_in[4];
    const float* bih_f  = (const float*)d_in[5];
    const float* bhh_f  = (const float*)d_in[6];
    const float* Wih_b  = (const float*)d_in[7];
    // d_in[8] (Whh_b) unused: backward LSTM runs exactly one step from zero state
    const float* bih_b  = (const float*)d_in[9];
    const float* bhh_b  = (const float*)d_in[10];
    const float* fc0_w  = (const float*)d_in[11];
    const float* fc0_b  = (const float*)d_in[12];
    const float* fc1_w  = (const float*)d_in[13];
    const float* fc1_b  = (const float*)d_in[14];
    // d_in[15..16] (fc2) unused: head term is constant over softmax axis
    const float* fc3_w  = (const float*)d_in[17];
    const float* fc3_b  = (const float*)d_in[18];
    const float* pred_w = (const float*)d_in[19];
    const float* pred_b = (const float*)d_in[20];
    float* out = (float*)d_out;

    fused_kernel<<<NSM, 512>>>(x, enc, mask, Wih_f, Whh_f, bih_f, bhh_f,
                               Wih_b, bih_b, bhh_b,
                               fc0_w, fc0_b, fc1_w, fc1_b, fc3_w, fc3_b,
                               pred_w, pred_b, out);
}

// round 17
// speedup vs baseline: 1.1246x; 1.0557x over previous
#include <cuda_runtime.h>

// Problem constants
#define BB 4
#define TT 16
#define NN 512
#define FF 5
#define HH 64
#define SS 2048           // B*N sequences
#define GG 256            // 4*H gates
#define R4 206            // RR/4 float4 per relation row
#define NSM 152           // GB300 SM count -> persistent 1 CTA/SM
#define NPAIR (NN*NN)     // 262144 relation pairs
#define NCHUNK (NPAIR/32) // 8192 32-pair chunks
#define CAPB (NCHUNK/2)   // B-half drains [0,CAPB); A-half drains [CAPB,NCHUNK)
// h k-major layout with 16B skew per 16-k block: conflict-free kb access
#define KOFF(k) ((k)*8 + ((k)>>4)*4)
#define HBUF 544          // one h buffer (64 k * 8 seqs + skew)

typedef unsigned long long ull;

// Scratch (device globals; no allocation allowed).
// g_relw: only entries with rel_mask==0 are ever written; masked entries stay
// 0.0 (static zero-init) and are annihilated by the -1e9 mask in the softmax,
// exactly as in the reference (exp underflows to 0 in fp32). Deterministic.
__device__ float g_relw[NPAIR];
__device__ float g_tail[SS];      // leaky(out . fc3_w + fc3_b)
__device__ float g_q[SS];         // out . pred_w[64:128]
__device__ float g_p0[SS];        // out . pred_w[0:64]

// Grid-wide barrier (generation-based; replay-safe) + split work tickets.
__device__ unsigned int g_bar_count = 0;
__device__ unsigned int g_bar_gen   = 0;
__device__ unsigned int g_ticketB   = 0;   // B-half region [0, CAPB)
__device__ unsigned int g_ticketA   = 0;   // A-half region [CAPB, NCHUNK)

__device__ __forceinline__ float leaky(float v) { return v > 0.f ? v : 0.01f * v; }

// MUFU.TANH-based activations (sm_75+): tanh = 1 MUFU; sigmoid via
// 0.5 + 0.5*tanh(x/2) = 1 MUFU + 2 FMA.
__device__ __forceinline__ float tanhft(float v) {
    float r;
    asm("tanh.approx.f32 %0, %1;" : "=f"(r) : "f"(v));
    return r;
}
__device__ __forceinline__ float sigm(float v) {
    float r;
    asm("tanh.approx.f32 %0, %1;" : "=f"(r) : "f"(0.5f * v));
    return 0.5f + 0.5f * r;
}

__device__ __forceinline__ void barn(int id, int cnt) {
    asm volatile("bar.sync %0, %1;" :: "r"(id), "r"(cnt) : "memory");
}

// packed f32x2 helpers (FFMA2/FADD2 — MOV-free operands from double2 loads)
__device__ __forceinline__ void fma2(ull& d, ull a, ull b) {
    asm("fma.rn.f32x2 %0, %1, %2, %3;" : "=l"(d) : "l"(a), "l"(b), "l"(d));
}
__device__ __forceinline__ ull add2(ull a, ull b) {
    ull d;
    asm("add.rn.f32x2 %0, %1, %2;" : "=l"(d) : "l"(a), "l"(b));
    return d;
}
__device__ __forceinline__ ull pack2(float lo, float hi) {
    ull r;
    asm("mov.b64 %0, {%1, %2};" : "=l"(r) : "f"(lo), "f"(hi));
    return r;
}
__device__ __forceinline__ void unpack2(ull a, float& lo, float& hi) {
    asm("mov.b64 {%0, %1}, %2;" : "=f"(lo), "=f"(hi) : "l"(a));
}
#define D2L __double_as_longlong

// One 824-length dot product, 32 lanes cooperating; returns lane-0 sum.
__device__ __forceinline__ float row_dot(const float4* __restrict__ row,
                                         const float4* __restrict__ wsm,
                                         int lane) {
    float4 a0 = __ldcs(row + lane);
    float4 a1 = __ldcs(row + lane + 32);
    float4 a2 = __ldcs(row + lane + 64);
    float4 a3 = __ldcs(row + lane + 96);
    float4 a4 = __ldcs(row + lane + 128);
    float4 a5 = __ldcs(row + lane + 160);
    float4 a6 = (lane < 14) ? __ldcs(row + lane + 192)
                            : make_float4(0.f, 0.f, 0.f, 0.f);
    float s = 0.f;
    float4 w;
    w = wsm[lane];       s += a0.x*w.x + a0.y*w.y + a0.z*w.z + a0.w*w.w;
    w = wsm[lane + 32];  s += a1.x*w.x + a1.y*w.y + a1.z*w.z + a1.w*w.w;
    w = wsm[lane + 64];  s += a2.x*w.x + a2.y*w.y + a2.z*w.z + a2.w*w.w;
    w = wsm[lane + 96];  s += a3.x*w.x + a3.y*w.y + a3.z*w.z + a3.w*w.w;
    w = wsm[lane + 128]; s += a4.x*w.x + a4.y*w.y + a4.z*w.z + a4.w*w.w;
    w = wsm[lane + 160]; s += a5.x*w.x + a5.y*w.y + a5.z*w.z + a5.w*w.w;
    if (lane < 14) {
        w = wsm[lane + 192];
        s += a6.x*w.x + a6.y*w.y + a6.z*w.z + a6.w*w.w;
    }
#pragma unroll
    for (int o = 16; o; o >>= 1) s += __shfl_xor_sync(0xffffffffu, s, o);
    return s;
}

// Drain relw tickets from [regbase + counter, regbase + count) — ballot mask
// scan + up-to-3-row batches (21 LDG.128 in flight).
__device__ __forceinline__ void relw_drain(
    unsigned int* counter, int regbase, int regcount,
    const float* __restrict__ enc, const float* __restrict__ rel_mask,
    const float4* __restrict__ wsm, float fb, int lane)
{
    for (;;) {
        unsigned int tk;
        if (lane == 0) tk = atomicAdd(counter, 1u);
        tk = __shfl_sync(0xffffffffu, tk, 0);
        if (tk >= (unsigned int)regcount) break;
        int pb = (regbase + (int)tk) * 32;
        float mv = rel_mask[pb + lane];         // coalesced 128B load
        unsigned act = __ballot_sync(0xffffffffu, mv == 0.f);
        while (act) {
            int b0 = __ffs(act) - 1; act &= act - 1;
            int b1 = -1, b2 = -1;
            if (act) { b1 = __ffs(act) - 1; act &= act - 1; }
            if (act) { b2 = __ffs(act) - 1; act &= act - 1; }
            const float4* r0 = (const float4*)enc + (long long)(pb + b0) * R4;
            float s0 = row_dot(r0, wsm, lane);
            float s1 = 0.f, s2 = 0.f;
            if (b1 >= 0) {
                const float4* r1 = (const float4*)enc + (long long)(pb + b1) * R4;
                s1 = row_dot(r1, wsm, lane);
            }
            if (b2 >= 0) {
                const float4* r2 = (const float4*)enc + (long long)(pb + b2) * R4;
                s2 = row_dot(r2, wsm, lane);
            }
            if (lane == 0) {
                g_relw[pb + b0] = leaky(s0 + fb);
                if (b1 >= 0) g_relw[pb + b1] = leaky(s1 + fb);
                if (b2 >= 0) g_relw[pb + b2] = leaky(s2 + fb);
            }
        }
    }
}

// ---------------------------------------------------------------------------
// LSTM engine v6 (R14): 256 threads, up to 8 sequences. Seq-packed FFMA2
// recurrence; fused activation/update in registers; MUFU activations;
// 1 barrier/step; h double-buffered.
// ---------------------------------------------------------------------------
__device__ __forceinline__ void lstm_engine(
    int t256, int sbase, int ns,
    const float* __restrict__ x,
    const float* __restrict__ Whh_f,
    const float* __restrict__ Wih_b,
    const float* __restrict__ bih_b, const float* __restrict__ bhh_b,
    const float* __restrict__ fc0_w, const float* __restrict__ fc0_b,
    const float* __restrict__ fc3_w, const float* __restrict__ fc3_b,
    const float* __restrict__ pred_w,
    const float* __restrict__ wihs,   // smem [GG*FF]
    const float* __restrict__ bsumS,  // smem [GG] (bih_f+bhh_f)
    float* __restrict__ xs,      // [8*TT*FF]
    float* __restrict__ hb0,     // [HBUF] h buffer 0 (read at even t)
    float* __restrict__ hb1,     // [HBUF] h buffer 1
    float* __restrict__ last,    // [8*2*HH]
    float* __restrict__ outb,    // [8*HH]
    int barid)
{
    const int w    = t256 >> 5, lane = t256 & 31;
    const int kb   = lane >> 3, gl   = lane & 7;
    const int u    = w * 8 + gl;           // this thread's unit 0..63
    const int kbase = kb * 16;             // this thread's k range
    // reduce-scatter final ownership: seqs s0, s0+1 (a packed pair)
    const int s0 = ((lane & 8) ? 4 : 0) + ((lane & 16) ? 2 : 0);
    const bool hi8  = (lane & 8)  != 0;
    const bool hi16 = (lane & 16) != 0;

    // Recurrent weights for gate rows {u, 64+u, 128+u, 192+u}, k-range kbase..
    float whr[4][16];
#pragma unroll
    for (int gt = 0; gt < 4; gt++) {
        const float4* wr = (const float4*)(Whh_f + (gt * HH + u) * HH + kbase);
#pragma unroll
        for (int q = 0; q < 4; q++) {
            float4 v = wr[q];
            whr[gt][4*q] = v.x; whr[gt][4*q+1] = v.y;
            whr[gt][4*q+2] = v.z; whr[gt][4*q+3] = v.w;
        }
    }
    // Input weights + bias for the same 4 gate rows (from smem staging)
    float wih[4][FF], bsum[4];
#pragma unroll
    for (int gt = 0; gt < 4; gt++) {
#pragma unroll
        for (int f = 0; f < FF; f++) wih[gt][f] = wihs[(gt * HH + u) * FF + f];
        bsum[gt] = bsumS[gt * HH + u];
    }

    // Stage x (zero-fill inactive seqs), zero read-buffer h
    for (int i = t256; i < 8 * TT * FF; i += 256) {
        float v = 0.f;
        if (i < ns * TT * FF) {
            int s = i / (TT * FF), r = i - s * (TT * FF);
            int t = r / FF, f = r - t * FF;
            int sg = sbase + s;
            int b = sg >> 9, n = sg & (NN - 1);
            v = x[((b * TT + t) * NN + n) * FF + f];
        }
        xs[i] = v;
    }
    for (int i = t256; i < HBUF; i += 256) hb0[i] = 0.f;
    float c0 = 0.f, c1 = 0.f;        // cell state for (u,s0), (u,s0+1)
    float hA = 0.f, hB = 0.f;        // final h values (kept for 'last')
    barn(barid, 256);

    // ---- forward recurrence: ONE barrier per step, h double-buffered ----
#pragma unroll 1
    for (int t = 0; t < TT; t++) {
        const float* hr = (t & 1) ? hb1 : hb0;   // read buffer
        float*       hw = (t & 1) ? hb0 : hb1;   // write buffer

        // Packed accumulators: acc2[gt][p] = f32x2 sums for seqs (2p, 2p+1)
        ull acc2[4][4];
#pragma unroll
        for (int gt = 0; gt < 4; gt++)
#pragma unroll
            for (int p = 0; p < 4; p++) acc2[gt][p] = 0ull;

#pragma unroll
        for (int j = 0; j < 16; j++) {
            const double2* hp = (const double2*)(hr + KOFF(kbase + j));
            double2 d0 = hp[0];            // pairs (s0,s1), (s2,s3)
            double2 d1 = hp[1];            // pairs (s4,s5), (s6,s7)
#pragma unroll
            for (int gt = 0; gt < 4; gt++) {
                ull wp = pack2(whr[gt][j], whr[gt][j]);
                fma2(acc2[gt][0], D2L(d0.x), wp);
                fma2(acc2[gt][1], D2L(d0.y), wp);
                fma2(acc2[gt][2], D2L(d1.x), wp);
                fma2(acc2[gt][3], D2L(d1.y), wp);
            }
        }

        // Packed reduce-scatter over the 4 kb lane-groups (xor 8, xor 16):
        // lane ends with ONE packed pair = full sums for (s0, s0+1).
        ull red[4];
#pragma unroll
        for (int gt = 0; gt < 4; gt++) {
            ull t2[2];
#pragma unroll
            for (int p = 0; p < 2; p++) {
                ull send = hi8 ? acc2[gt][p]     : acc2[gt][p + 2];
                ull keep = hi8 ? acc2[gt][p + 2] : acc2[gt][p];
                t2[p] = add2(keep, __shfl_xor_sync(0xffffffffu, send, 8));
            }
            {
                ull send = hi16 ? t2[0] : t2[1];
                ull keep = hi16 ? t2[1] : t2[0];
                red[gt] = add2(keep, __shfl_xor_sync(0xffffffffu, send, 16));
            }
        }

        // x-part + bias, then FUSED activation + cell update (in registers)
        {
            const float* xtA = xs + s0 * (TT * FF) + t * FF;
            const float* xtB = xtA + (TT * FF);
            float pA[4], pB[4];
#pragma unroll
            for (int gt = 0; gt < 4; gt++) {
                float r0, r1;
                unpack2(red[gt], r0, r1);
                float a0 = r0 + bsum[gt];
                float a1 = r1 + bsum[gt];
#pragma unroll
                for (int f = 0; f < FF; f++) {
                    float wv = wih[gt][f];
                    a0 += xtA[f] * wv;
                    a1 += xtB[f] * wv;
                }
                pA[gt] = a0; pB[gt] = a1;
            }
            float iA = sigm(pA[0]), fA = sigm(pA[1]);
            float gA = tanhft(pA[2]), oA = sigm(pA[3]);
            c0 = fA * c0 + iA * gA;
            hA = oA * tanhft(c0);
            float iB = sigm(pB[0]), fB = sigm(pB[1]);
            float gB = tanhft(pB[2]), oB = sigm(pB[3]);
            c1 = fB * c1 + iB * gB;
            hB = oB * tanhft(c1);
            hw[KOFF(u) + s0]     = hA;
            hw[KOFF(u) + s0 + 1] = hB;
        }
        barn(barid, 256);
    }

    // h_fwd -> last[:, 0:64] (straight from registers)
    last[s0 * 2 * HH + u]       = hA;
    last[(s0 + 1) * 2 * HH + u] = hB;

    // ---- backward LSTM: one step from zero state on x[T-1] (f unused) ----
    {
        const float* xtA = xs + s0 * (TT * FF) + (TT - 1) * FF;
        const float* xtB = xtA + (TT * FF);
        float pA[4], pB[4];
#pragma unroll
        for (int gt = 0; gt < 4; gt++) {
            if (gt == 1) continue;               // forget gate irrelevant
            float bb = bih_b[gt * HH + u] + bhh_b[gt * HH + u];
            float a0 = bb, a1 = bb;
#pragma unroll
            for (int f = 0; f < FF; f++) {
                float wv = Wih_b[(gt * HH + u) * FF + f];
                a0 += xtA[f] * wv;
                a1 += xtB[f] * wv;
            }
            pA[gt] = a0; pB[gt] = a1;
        }
        float iA = sigm(pA[0]), gA = tanhft(pA[2]), oA = sigm(pA[3]);
        float iB = sigm(pB[0]), gB = tanhft(pB[2]), oB = sigm(pB[3]);
        last[s0 * 2 * HH + HH + u]       = oA * tanhft(iA * gA);  // f*c0 = 0
        last[(s0 + 1) * 2 * HH + HH + u] = oB * tanhft(iB * gB);
    }
    barn(barid, 256);

    // ---- fc0 + leaky: threads (su,uu) and (su+4,uu) ----
    {
        const int uu = t256 & 63, su = t256 >> 6;
        const float4* w4 = (const float4*)(fc0_w + uu * 2 * HH);
        const float4* la = (const float4*)(last + su * 2 * HH);
        const float4* lb = (const float4*)(last + (su + 4) * 2 * HH);
        float a0 = 0.f, a1 = 0.f, b0 = 0.f, b1 = 0.f;
#pragma unroll
        for (int j = 0; j < 2 * HH / 4; j++) {
            float4 wv = w4[j];
            float4 va = la[j], vb = lb[j];
            a0 += wv.x * va.x + wv.y * va.y;
            a1 += wv.z * va.z + wv.w * va.w;
            b0 += wv.x * vb.x + wv.y * vb.y;
            b1 += wv.z * vb.z + wv.w * vb.w;
        }
        float fb = fc0_b[uu];
        outb[su * HH + uu]       = leaky(fb + a0 + a1);
        outb[(su + 4) * HH + uu] = leaky(fb + b0 + b1);
    }
    barn(barid, 256);

    // ---- epilogue scalars: one warp per sequence (3 dots fused) ----
    if (w < ns) {
        int sg = sbase + w;
        const float* o = outb + w * HH;
        float o_lo = o[lane], o_hi = o[lane + 32];
        float v0 = o_lo * fc3_w[lane]        + o_hi * fc3_w[lane + 32];
        float v1 = o_lo * pred_w[HH + lane]  + o_hi * pred_w[HH + lane + 32];
        float v2 = o_lo * pred_w[lane]       + o_hi * pred_w[lane + 32];
#pragma unroll
        for (int off = 16; off; off >>= 1) {
            v0 += __shfl_xor_sync(0xffffffffu, v0, off);
            v1 += __shfl_xor_sync(0xffffffffu, v1, off);
            v2 += __shfl_xor_sync(0xffffffffu, v2, off);
        }
        if (lane == 0) {
            g_tail[sg] = leaky(v0 + fc3_b[0]);
            g_q[sg]    = v1;
            g_p0[sg]   = v2;
        }
    }
}

// ---------------------------------------------------------------------------
// Persistent kernel: 152 CTAs x 512 threads (one per SM, one wave).
//   warps 0-7 : LSTM engine A (seqs 0..7) immediately, THEN drain the second
//               half of the relw tickets ([CAPB, NCHUNK)).
//   warps 8-15: drain the first half of relw ([0, CAPB)), THEN engine B.
// Both relw segments overlap the other half's engine -> total ~= T_E + W/2.
// Grid barrier, then phase 3: masked softmax + prediction (warp per row).
// ---------------------------------------------------------------------------
__global__ __launch_bounds__(512, 1) void fused_kernel(
    const float* __restrict__ x,
    const float* __restrict__ enc,
    const float* __restrict__ rel_mask,
    const float* __restrict__ Wih_f, const float* __restrict__ Whh_f,
    const float* __restrict__ bih_f, const float* __restrict__ bhh_f,
    const float* __restrict__ Wih_b,
    const float* __restrict__ bih_b, const float* __restrict__ bhh_b,
    const float* __restrict__ fc0_w, const float* __restrict__ fc0_b,
    const float* __restrict__ fc1_w, const float* __restrict__ fc1_b,
    const float* __restrict__ fc3_w, const float* __restrict__ fc3_b,
    const float* __restrict__ pred_w, const float* __restrict__ pred_b,
    float* __restrict__ out)
{
    __shared__ float4 wsm[R4];                  // fc1 weights
    __shared__ float wihs[GG * FF];             // Wih_f staged
    __shared__ float bsumS[GG];                 // bih_f + bhh_f
    __shared__ float xsA[8 * TT * FF], xsB[8 * TT * FF];
    __shared__ __align__(16) float h0A[HBUF], h1A[HBUF];
    __shared__ __align__(16) float h0B[HBUF], h1B[HBUF];
    __shared__ __align__(16) float lastA[8 * 2 * HH], lastB[8 * 2 * HH];
    __shared__ float outA[8 * HH], outB[8 * HH];

    int cta = blockIdx.x;
    int tid = threadIdx.x;
    int wid = tid >> 5, lane = tid & 31;

    // Snapshot barrier generation BEFORE any arrival can happen this launch.
    unsigned int my_gen = *((volatile unsigned int*)&g_bar_gen);

    // Stage shared weights (fc1, Wih_f, bias sums) once, all 512 threads.
    {
        const float4* w4g = (const float4*)fc1_w;
        for (int i = tid; i < R4; i += 512) wsm[i] = w4g[i];
        for (int i = tid; i < GG * FF; i += 512) wihs[i] = Wih_f[i];
        for (int i = tid; i < GG; i += 512) bsumS[i] = bih_f[i] + bhh_f[i];
    }
    __syncthreads();

    // Sequence range: 2048 = 152*13 + 72  -> cnt = 13 or 14
    int base = 13 * cta + (cta < 72 ? cta : 72);
    int cnt  = 13 + (cta < 72 ? 1 : 0);
    float fb = fc1_b[0];

    if (wid < 8) {
        // ==== Half A: engine A first, then relw suffix [CAPB, NCHUNK) ======
        lstm_engine(tid, base, 8, x, Whh_f, Wih_b, bih_b, bhh_b,
                    fc0_w, fc0_b, fc3_w, fc3_b, pred_w, wihs, bsumS,
                    xsA, h0A, h1A, lastA, outA, /*barid=*/1);
        relw_drain(&g_ticketA, CAPB, NCHUNK - CAPB, enc, rel_mask,
                   (const float4*)wsm, fb, lane);
    } else {
        // ==== Half B: relw prefix [0, CAPB), then engine B =================
        relw_drain(&g_ticketB, 0, CAPB, enc, rel_mask,
                   (const float4*)wsm, fb, lane);
        lstm_engine(tid - 256, base + 8, cnt - 8, x, Whh_f, Wih_b, bih_b, bhh_b,
                    fc0_w, fc0_b, fc3_w, fc3_b, pred_w, wihs, bsumS,
                    xsB, h0B, h1B, lastB, outB, /*barid=*/2);
    }

    // ===================== Grid-wide barrier ===============================
    __threadfence();                    // publish g_relw/g_tail/g_q/g_p0
    __syncthreads();                    // join the two halves
    if (tid == 0) {
        unsigned int old = atomicAdd(&g_bar_count, 1u);
        if (old == NSM - 1) {
            g_bar_count = 0;            // all CTAs have arrived
            g_ticketA = 0;              // reset work tickets for next launch
            g_ticketB = 0;
            __threadfence();
            atomicAdd(&g_bar_gen, 1u);  // release
        }
        while (*((volatile unsigned int*)&g_bar_gen) == my_gen) { }
    }
    __syncthreads();
    __threadfence();                    // acquire

    // ====== Phase 3: masked softmax + prediction (one warp per row) ========
    if (wid < cnt) {
        int sg = base + wid;
        int b = sg >> 9, n = sg & (NN - 1);
        const float4* m4 = (const float4*)(rel_mask + (long long)n * NN);
        const float4* r4 = (const float4*)(g_relw  + (long long)n * NN);
        const float4* t4 = (const float4*)(g_tail + b * NN);
        const float4* q4 = (const float4*)(g_q    + b * NN);

        float4 l[4];
        float mx = -1e30f;
#pragma unroll
        for (int j = 0; j < 4; j++) {
            int idx = j * 32 + lane;
            float4 mv = m4[idx], rv = r4[idx], tv = t4[idx];
            l[j].x = mv.x + rv.x + tv.x;
            l[j].y = mv.y + rv.y + tv.y;
            l[j].z = mv.z + rv.z + tv.z;
            l[j].w = mv.w + rv.w + tv.w;
            mx = fmaxf(mx, fmaxf(fmaxf(l[j].x, l[j].y), fmaxf(l[j].z, l[j].w)));
        }
#pragma unroll
        for (int o = 16; o; o >>= 1) mx = fmaxf(mx, __shfl_xor_sync(0xffffffffu, mx, o));

        float se = 0.f, sq = 0.f;
#pragma unroll
        for (int j = 0; j < 4; j++) {
            int idx = j * 32 + lane;
            float4 qv = q4[idx];
            float e0 = __expf(l[j].x - mx);
            float e1 = __expf(l[j].y - mx);
            float e2 = __expf(l[j].z - mx);
            float e3 = __expf(l[j].w - mx);
            se += (e0 + e1) + (e2 + e3);
            sq += (e0 * qv.x + e1 * qv.y) + (e2 * qv.z + e3 * qv.w);
        }
#pragma unroll
        for (int o = 16; o; o >>= 1) {
            se += __shfl_xor_sync(0xffffffffu, se, o);
            sq += __shfl_xor_sync(0xffffffffu, sq, o);
        }
        if (lane == 0)
            out[sg] = leaky(g_p0[sg] + sq / se + pred_b[0]);
    }
}

// ---------------------------------------------------------------------------
extern "C" void kernel_launch(void* const* d_in, const int* in_sizes, int n_in,
                              void* d_out, int out_size) {
    const float* x      = (const float*)d_in[0];
    const float* enc    = (const float*)d_in[1];
    const float* mask   = (const float*)d_in[2];
    const float* Wih_f  = (const float*)d_in[3];
    const float* Whh_f  = (const float*)d_in[4];
    const float* bih_f  = (const float*)d_in[5];
    const float* bhh_f  = (const float*)d_in[6];
    const float* Wih_b  = (const float*)d_in[7];
    // d_in[8] (Whh_b) unused: backward LSTM runs exactly one step from zero state
    const float* bih_b  = (const float*)d_in[9];
    const float* bhh_b  = (const float*)d_in[10];
    const float* fc0_w  = (const float*)d_in[11];
    const float* fc0_b  = (const float*)d_in[12];
    const float* fc1_w  = (const float*)d_in[13];
    const float* fc1_b  = (const float*)d_in[14];
    // d_in[15..16] (fc2) unused: head term is constant over softmax axis
    const float* fc3_w  = (const float*)d_in[17];
    const float* fc3_b  = (const float*)d_in[18];
    const float* pred_w = (const float*)d_in[19];
    const float* pred_b = (const float*)d_in[20];
    float* out = (float*)d_out;

    fused_kernel<<<NSM, 512>>>(x, enc, mask, Wih_f, Whh_f, bih_f, bhh_f,
                               Wih_b, bih_b, bhh_b,
                               fc0_w, fc0_b, fc1_w, fc1_b, fc3_w, fc3_b,
                               pred_w, pred_b, out);
}